// round 4
// baseline (speedup 1.0000x reference)
#include <cuda_runtime.h>

#define BATCH 32768
#define TT 21
#define FIN 126
#define UU 8
#define GG 32
#define NC 27

// Phase A tiling
#define PA_THREADS 64
#define PA_ROWS 128
#define XS_STRIDE 130                 // floats per padded row
#define XS_BYTES (PA_ROWS * XS_STRIDE * 4)      // 66560
#define WP_BYTES (FIN * 8 * 16)                 // 16128
#define SMEM_A (XS_BYTES + WP_BYTES + 128)

typedef unsigned long long ull;

// Scratch: gate pre-activations, per (b,t): 8 units x float4(i,f,g,o)  (88 MB)
__device__ float g_z1[(size_t)BATCH * TT * GG];

// ---------------- packed f32x2 helpers ----------------
__device__ __forceinline__ ull fma2(ull a, ull b, ull c) {
    ull d;
    asm("fma.rn.f32x2 %0, %1, %2, %3;" : "=l"(d) : "l"(a), "l"(b), "l"(c));
    return d;
}
__device__ __forceinline__ ull add2(ull a, ull b) {
    ull d;
    asm("add.rn.f32x2 %0, %1, %2;" : "=l"(d) : "l"(a), "l"(b));
    return d;
}
__device__ __forceinline__ ull bcast2(float v) {
    ull d;
    asm("mov.b64 %0, {%1, %2};" : "=l"(d) : "f"(v), "f"(v));
    return d;
}
__device__ __forceinline__ ull pack2(float lo, float hi) {
    ull d;
    asm("mov.b64 %0, {%1, %2};" : "=l"(d) : "f"(lo), "f"(hi));
    return d;
}
__device__ __forceinline__ void unpack2(float& lo, float& hi, ull v) {
    asm("mov.b64 {%0, %1}, %2;" : "=f"(lo), "=f"(hi) : "l"(v));
}

// Fast activations: MUFU-based, rel err ~1e-6 (threshold 1e-3)
__device__ __forceinline__ float sigm(float x) {
    return __fdividef(1.0f, 1.0f + __expf(-x));
}
__device__ __forceinline__ float tanhg(float x) {
    return __fdividef(2.0f, 1.0f + __expf(-2.0f * x)) - 1.0f;
}

// ---------------- Phase A: input projection (B*T,126) @ (126,32) ----------------
// 64 threads / 128 contiguous rows per block, x staged through smem (coalesced).
// Thread i computes rows i and i+64 (2-row weight amortization).
__global__ __launch_bounds__(PA_THREADS)
void input_proj_kernel(const float* __restrict__ x,
                       const float* __restrict__ W1k,
                       const float* __restrict__ b1) {
    extern __shared__ char dynsmem[];
    float* xs = (float*)dynsmem;                                 // [128][130]
    ulonglong2* sWp = (ulonglong2*)(dynsmem + XS_BYTES);         // [126*8]
    ull* sB = (ull*)(dynsmem + XS_BYTES + WP_BYTES);             // [16]

    int tid = threadIdx.x;

    // Weights: sWp[f*8+g2] = 4 floats of column f (gates 4g2..4g2+3) as 2 packs
    for (int i = tid; i < FIN * 8; i += PA_THREADS) {
        int f = i >> 3, g2 = i & 7;
        const float* w = W1k + f * GG + 4 * g2;
        sWp[i] = make_ulonglong2(pack2(w[0], w[1]), pack2(w[2], w[3]));
    }
    if (tid < 16)
        sB[tid] = pack2(b1[2 * tid], b1[2 * tid + 1]);

    // Stage x: block slab is contiguous (128 rows * 126 floats)
    const float2* gx = (const float2*)(x + (size_t)blockIdx.x * PA_ROWS * FIN);
    for (int i = tid; i < PA_ROWS * (FIN / 2); i += PA_THREADS) {
        int row = i / (FIN / 2);
        int col = i - row * (FIN / 2);
        *(float2*)(xs + row * XS_STRIDE + 2 * col) = gx[i];
    }
    __syncthreads();

    const float2* xr0 = (const float2*)(xs + tid * XS_STRIDE);
    const float2* xr1 = (const float2*)(xs + (tid + 64) * XS_STRIDE);

    ull a0[16], a1[16];
#pragma unroll
    for (int g = 0; g < 16; ++g) { a0[g] = sB[g]; a1[g] = sB[g]; }

#pragma unroll 9
    for (int f2 = 0; f2 < FIN / 2; ++f2) {
        float2 v0 = xr0[f2];
        float2 v1 = xr1[f2];
        ull b00 = bcast2(v0.x), b01 = bcast2(v0.y);
        ull b10 = bcast2(v1.x), b11 = bcast2(v1.y);
#pragma unroll
        for (int g2 = 0; g2 < 8; ++g2) {
            ulonglong2 wA = sWp[(2 * f2) * 8 + g2];
            ulonglong2 wB = sWp[(2 * f2 + 1) * 8 + g2];
            a0[2 * g2]     = fma2(b00, wA.x, a0[2 * g2]);
            a0[2 * g2 + 1] = fma2(b00, wA.y, a0[2 * g2 + 1]);
            a1[2 * g2]     = fma2(b10, wA.x, a1[2 * g2]);
            a1[2 * g2 + 1] = fma2(b10, wA.y, a1[2 * g2 + 1]);
            a0[2 * g2]     = fma2(b01, wB.x, a0[2 * g2]);
            a0[2 * g2 + 1] = fma2(b01, wB.y, a0[2 * g2 + 1]);
            a1[2 * g2]     = fma2(b11, wB.x, a1[2 * g2]);
            a1[2 * g2 + 1] = fma2(b11, wB.y, a1[2 * g2 + 1]);
        }
    }

    // Epilogue: unpack, store per-unit float4 (i_k, f_k, g_k, o_k)
    float ga0[GG], ga1[GG];
#pragma unroll
    for (int g = 0; g < 16; ++g) {
        unpack2(ga0[2 * g], ga0[2 * g + 1], a0[g]);
        unpack2(ga1[2 * g], ga1[2 * g + 1], a1[g]);
    }
    size_t gr0 = (size_t)blockIdx.x * PA_ROWS + tid;
    size_t gr1 = gr0 + 64;
    float4* o0 = (float4*)(g_z1 + gr0 * GG);
    float4* o1 = (float4*)(g_z1 + gr1 * GG);
#pragma unroll
    for (int k = 0; k < 8; ++k) {
        o0[k] = make_float4(ga0[k], ga0[8 + k], ga0[16 + k], ga0[24 + k]);
        o1[k] = make_float4(ga1[k], ga1[8 + k], ga1[16 + k], ga1[24 + k]);
    }
}

// ---------------- Phase B: octet-per-element ----------------
// 8 threads per element, thread k owns unit k. w1 in regs, w2 in smem,
// z register double-buffered, split fma chains.
__global__ __launch_bounds__(128)
void recurrent_kernel(const float* __restrict__ W1r, const float* __restrict__ W2k,
                      const float* __restrict__ W2r, const float* __restrict__ b2,
                      const float* __restrict__ Wd, const float* __restrict__ bd,
                      float* __restrict__ out) {
    __shared__ ulonglong2 sw2a[64];   // W2k: [j*8+k] = (pack(if), pack(go))
    __shared__ ulonglong2 sw2b[64];   // W2r: same layout

    int tid = threadIdx.x;
    if (tid < 64) {
        int j = tid >> 3, kk = tid & 7;
        const float* p = W2k + j * GG;
        sw2a[tid] = make_ulonglong2(pack2(p[kk], p[8 + kk]), pack2(p[16 + kk], p[24 + kk]));
    } else {
        int i = tid - 64;
        int j = i >> 3, kk = i & 7;
        const float* p = W2r + j * GG;
        sw2b[i] = make_ulonglong2(pack2(p[kk], p[8 + kk]), pack2(p[16 + kk], p[24 + kk]));
    }
    __syncthreads();

    int gtid = blockIdx.x * blockDim.x + tid;
    int e = gtid >> 3;
    int lane = tid & 31;
    int k = lane & 7;
    int obase = lane & 24;

    // Layer-1 recurrent weights in registers (16 ULL = 32 regs)
    ull w1if[8], w1go[8];
#pragma unroll
    for (int j = 0; j < 8; ++j) {
        const float* r1 = W1r + j * GG;
        w1if[j] = pack2(r1[k], r1[8 + k]);
        w1go[j] = pack2(r1[16 + k], r1[24 + k]);
    }
    ull b2if = pack2(b2[k], b2[8 + k]);
    ull b2go = pack2(b2[16 + k], b2[24 + k]);

    float h1 = 0.f, c1 = 0.f, h2 = 0.f, c2 = 0.f;
    const ulonglong2* zbase = (const ulonglong2*)(g_z1 + (size_t)e * TT * GG) + k;

    ulonglong2 zz = zbase[0];   // prefetch t=0

    for (int t = 0; t < TT; ++t) {
        ull zifA = zz.x, zgoA = zz.y;
        if (t < TT - 1) zz = zbase[(t + 1) * 8];   // prefetch next step

        // ---- layer 1 (split 4+4 chains) ----
        ull zifB = 0ull, zgoB = 0ull;
#pragma unroll
        for (int j = 0; j < 4; ++j) {
            ull hb = bcast2(__shfl_sync(0xffffffffu, h1, obase | j));
            zifA = fma2(hb, w1if[j], zifA);
            zgoA = fma2(hb, w1go[j], zgoA);
        }
#pragma unroll
        for (int j = 4; j < 8; ++j) {
            ull hb = bcast2(__shfl_sync(0xffffffffu, h1, obase | j));
            zifB = fma2(hb, w1if[j], zifB);
            zgoB = fma2(hb, w1go[j], zgoB);
        }
        {
            ull zif = add2(zifA, zifB), zgo = add2(zgoA, zgoB);
            float zi, zf, zg, zo;
            unpack2(zi, zf, zif);
            unpack2(zg, zo, zgo);
            c1 = sigm(zf) * c1 + sigm(zi) * tanhg(zg);
            h1 = sigm(zo) * tanhg(c1);
        }

        // ---- layer 2 (a-chain: h1 terms; b-chain: h2 terms) ----
        zifA = b2if; zgoA = b2go; zifB = 0ull; zgoB = 0ull;
#pragma unroll
        for (int j = 0; j < 8; ++j) {
            ull ab = bcast2(__shfl_sync(0xffffffffu, h1, obase | j));
            ull bb = bcast2(__shfl_sync(0xffffffffu, h2, obase | j));
            ulonglong2 wa = sw2a[j * 8 + k];
            ulonglong2 wb = sw2b[j * 8 + k];
            zifA = fma2(ab, wa.x, zifA);
            zgoA = fma2(ab, wa.y, zgoA);
            zifB = fma2(bb, wb.x, zifB);
            zgoB = fma2(bb, wb.y, zgoB);
        }
        {
            ull zif = add2(zifA, zifB), zgo = add2(zgoA, zgoB);
            float zi, zf, zg, zo;
            unpack2(zi, zf, zif);
            unpack2(zg, zo, zgo);
            c2 = sigm(zf) * c2 + sigm(zi) * tanhg(zg);
            h2 = sigm(zo) * tanhg(c2);
        }
    }

    // ---- dense + softmax, distributed over octet ----
    float h2f[8];
#pragma unroll
    for (int j = 0; j < 8; ++j)
        h2f[j] = __shfl_sync(0xffffffffu, h2, obase | j);

    float lg[4];
#pragma unroll
    for (int q = 0; q < 4; ++q) {
        int m = q * 8 + k;
        float acc = (m < NC) ? bd[m] : -1e30f;
        if (m < NC) {
#pragma unroll
            for (int j = 0; j < 8; ++j) acc += h2f[j] * Wd[j * NC + m];
        }
        lg[q] = acc;
    }
    float mx = fmaxf(fmaxf(lg[0], lg[1]), fmaxf(lg[2], lg[3]));
#pragma unroll
    for (int off = 4; off >= 1; off >>= 1)
        mx = fmaxf(mx, __shfl_xor_sync(0xffffffffu, mx, off));
    float s = 0.f;
#pragma unroll
    for (int q = 0; q < 4; ++q) {
        float v = (q * 8 + k < NC) ? __expf(lg[q] - mx) : 0.f;
        lg[q] = v;
        s += v;
    }
#pragma unroll
    for (int off = 4; off >= 1; off >>= 1)
        s += __shfl_xor_sync(0xffffffffu, s, off);
    float inv = __fdividef(1.0f, s);
    float* op = out + (size_t)e * NC;
#pragma unroll
    for (int q = 0; q < 4; ++q) {
        int m = q * 8 + k;
        if (m < NC) op[m] = lg[q] * inv;
    }
}

// ---------------- launch ----------------
extern "C" void kernel_launch(void* const* d_in, const int* in_sizes, int n_in,
                              void* d_out, int out_size) {
    const float* x   = (const float*)d_in[0];
    const float* W1k = (const float*)d_in[1];
    const float* W1r = (const float*)d_in[2];
    const float* b1  = (const float*)d_in[3];
    const float* W2k = (const float*)d_in[4];
    const float* W2r = (const float*)d_in[5];
    const float* b2  = (const float*)d_in[6];
    const float* Wd  = (const float*)d_in[7];
    const float* bd  = (const float*)d_in[8];
    float* out = (float*)d_out;

    cudaFuncSetAttribute(input_proj_kernel,
                         cudaFuncAttributeMaxDynamicSharedMemorySize, SMEM_A);

    input_proj_kernel<<<(BATCH * TT) / PA_ROWS, PA_THREADS, SMEM_A>>>(x, W1k, b1);
    recurrent_kernel<<<(BATCH * 8) / 128, 128>>>(W1r, W2k, W2r, b2, Wd, bd, out);
}